// round 5
// baseline (speedup 1.0000x reference)
#include <cuda_runtime.h>
#include <cuda_bf16.h>
#include <cstdint>

#define NN    10000
#define EMAXX 160000
#define ETOT  (EMAXX + NN)

// ---------------- device scratch (no allocations allowed) ----------------
__device__ int   g_is64;
__device__ int   g_deg[NN];
__device__ float g_dinv[NN];
__device__ int   g_off[NN + 1];
__device__ int   g_cur[NN];
__device__ int   g_crow[ETOT];
__device__ float g_cnorm[ETOT];
__device__ float g_h[(size_t)NN * 512];               // fp32 activations (GEMM out)
__device__ __nv_bfloat16 g_ah[(size_t)NN * 512];      // A hi (SpMM out)
__device__ __nv_bfloat16 g_al[(size_t)NN * 512];      // A lo
__device__ __nv_bfloat16 g_wh[4 * 512 * 512];         // W^T hi, [N rows][K cols]
__device__ __nv_bfloat16 g_wl[4 * 512 * 512];         // W^T lo

__device__ __forceinline__ int ld_idx(const void* p, long long i) {
    if (g_is64) return (int)((const long long*)p)[i];
    return ((const int*)p)[i];
}

// ---------------- preprocessing (fused) ----------------
__global__ void k_init(const void* ei, int E) {
    int i = blockIdx.x * blockDim.x + threadIdx.x;
    if (i < NN) { g_deg[i] = 1; g_cur[i] = 0; }
    if (blockIdx.x == 0 && threadIdx.x < 32) {
        const long long* p = (const long long*)ei;
        int lim = (E < 64) ? E : 64;
        int bad = 0;
        for (int j = threadIdx.x; j < lim; j += 32) {
            long long v = p[j];
            bad |= (v < 0 || v >= NN);
        }
        unsigned m = __ballot_sync(0xFFFFFFFFu, bad);
        if (threadIdx.x == 0) g_is64 = (m == 0);
    }
}
__global__ void k_deg(const void* ei, int E) {
    int e = blockIdx.x * blockDim.x + threadIdx.x;
    if (e < E) atomicAdd(&g_deg[ld_idx(ei, (long long)E + e)], 1);
}
__global__ void k_scan() {
    __shared__ int s[1024];
    const int CH = 10;
    int t = threadIdx.x;
    int base = t * CH, loc[CH], sum = 0;
#pragma unroll
    for (int j = 0; j < CH; j++) {
        int idx = base + j;
        int v = (idx < NN) ? g_deg[idx] : 0;
        if (idx < NN) g_dinv[idx] = rsqrtf((float)v);
        loc[j] = sum; sum += v;
    }
    s[t] = sum;
    __syncthreads();
    for (int d = 1; d < 1024; d <<= 1) {
        int v = (t >= d) ? s[t - d] : 0;
        __syncthreads();
        s[t] += v;
        __syncthreads();
    }
    int excl = (t > 0) ? s[t - 1] : 0;
#pragma unroll
    for (int j = 0; j < CH; j++) {
        int idx = base + j;
        if (idx < NN) g_off[idx] = excl + loc[j];
    }
    if (t == 0) g_off[NN] = s[1023];
}
__global__ void k_fill(const void* ei, int E) {
    int e = blockIdx.x * blockDim.x + threadIdx.x;
    int tot = E + NN;
    if (e >= tot) return;
    int r, c;
    if (e < E) { r = ld_idx(ei, e); c = ld_idx(ei, (long long)E + e); }
    else { r = e - E; c = r; }
    int p = atomicAdd(&g_cur[c], 1);
    int idx = g_off[c] + p;
    g_crow[idx]  = r;
    g_cnorm[idx] = g_dinv[r] * g_dinv[c];
}

// all 4 weights: W [K,512] fp32 -> Wt hi/lo [512][K] bf16 (tiled transpose)
__global__ void k_wconv_all(const float* __restrict__ W1, const float* __restrict__ W2,
                            const float* __restrict__ W3, const float* __restrict__ W4,
                            __nv_bfloat16* __restrict__ whB, __nv_bfloat16* __restrict__ wlB) {
    __shared__ float t[32][33];
    int l = blockIdx.z;
    const float* W = (l == 0) ? W1 : (l == 1) ? W2 : (l == 2) ? W3 : W4;
    int K = (l == 0) ? 256 : 512;
    int k0 = blockIdx.x * 32, n0 = blockIdx.y * 32;
    if (k0 >= K) return;
    __nv_bfloat16* wh = whB + (size_t)l * 512 * 512;
    __nv_bfloat16* wl = wlB + (size_t)l * 512 * 512;
    int tx = threadIdx.x, ty = threadIdx.y;
    t[ty][tx] = W[(size_t)(k0 + ty) * 512 + n0 + tx];
    __syncthreads();
    float v = t[tx][ty];
    __nv_bfloat16 h = __float2bfloat16(v);
    float lo = v - __bfloat162float(h);
    size_t o = (size_t)(n0 + ty) * K + k0 + tx;
    wh[o] = h;
    wl[o] = __float2bfloat16(lo);
}

// ---------------- SpMM: acc fp32, write bf16 hi/lo split ----------------
__device__ __forceinline__ uint32_t pack2(float a, float b) {
    __nv_bfloat162 t = __floats2bfloat162_rn(a, b);
    return *(uint32_t*)&t;
}
template <int FD>
__global__ void k_spmm_split(const float* __restrict__ h,
                             __nv_bfloat16* __restrict__ ah,
                             __nv_bfloat16* __restrict__ al) {
    const int V = FD / 4;
    int node = blockIdx.x;
    int tid  = threadIdx.x;
    int s = g_off[node], e = g_off[node + 1];
    const float4* h4 = (const float4*)h;
    float4 acc = make_float4(0.f, 0.f, 0.f, 0.f);
    int i = s;
    for (; i + 4 <= e; i += 4) {
        int   r0 = g_crow[i],     r1 = g_crow[i + 1];
        int   r2 = g_crow[i + 2], r3 = g_crow[i + 3];
        float w0 = g_cnorm[i],     w1 = g_cnorm[i + 1];
        float w2 = g_cnorm[i + 2], w3 = g_cnorm[i + 3];
        float4 v0 = h4[(size_t)r0 * V + tid];
        float4 v1 = h4[(size_t)r1 * V + tid];
        float4 v2 = h4[(size_t)r2 * V + tid];
        float4 v3 = h4[(size_t)r3 * V + tid];
        acc.x += w0 * v0.x; acc.y += w0 * v0.y; acc.z += w0 * v0.z; acc.w += w0 * v0.w;
        acc.x += w1 * v1.x; acc.y += w1 * v1.y; acc.z += w1 * v1.z; acc.w += w1 * v1.w;
        acc.x += w2 * v2.x; acc.y += w2 * v2.y; acc.z += w2 * v2.z; acc.w += w2 * v2.w;
        acc.x += w3 * v3.x; acc.y += w3 * v3.y; acc.z += w3 * v3.z; acc.w += w3 * v3.w;
    }
    for (; i < e; i++) {
        int   r = g_crow[i];
        float w = g_cnorm[i];
        float4 v = h4[(size_t)r * V + tid];
        acc.x += w * v.x; acc.y += w * v.y; acc.z += w * v.z; acc.w += w * v.w;
    }
    float hx = __bfloat162float(__float2bfloat16(acc.x));
    float hy = __bfloat162float(__float2bfloat16(acc.y));
    float hz = __bfloat162float(__float2bfloat16(acc.z));
    float hw = __bfloat162float(__float2bfloat16(acc.w));
    uint2 uh, ul;
    uh.x = pack2(acc.x, acc.y); uh.y = pack2(acc.z, acc.w);
    ul.x = pack2(acc.x - hx, acc.y - hy); ul.y = pack2(acc.z - hz, acc.w - hw);
    size_t base = (size_t)node * FD + tid * 4;
    *(uint2*)(ah + base) = uh;
    *(uint2*)(al + base) = ul;
}

// ---------------- HMMA helpers ----------------
__device__ __forceinline__ uint32_t smem_u32(const void* p) {
    uint32_t a;
    asm("{ .reg .u64 t; cvta.to.shared.u64 t, %1; cvt.u32.u64 %0, t; }" : "=r"(a) : "l"(p));
    return a;
}
#define LDSM_X4(r0, r1, r2, r3, addr) \
    asm volatile("ldmatrix.sync.aligned.m8n8.x4.shared.b16 {%0,%1,%2,%3}, [%4];" \
        : "=r"(r0), "=r"(r1), "=r"(r2), "=r"(r3) : "r"(addr))
#define MMA16816(d, a0, a1, a2, a3, b0, b1) \
    asm volatile("mma.sync.aligned.m16n8k16.row.col.f32.bf16.bf16.f32 " \
        "{%0,%1,%2,%3}, {%4,%5,%6,%7}, {%8,%9}, {%0,%1,%2,%3};" \
        : "+f"((d)[0]), "+f"((d)[1]), "+f"((d)[2]), "+f"((d)[3]) \
        : "r"(a0), "r"(a1), "r"(a2), "r"(a3), "r"(b0), "r"(b1))
#define CP_ASYNC16(dst, src, sz) \
    asm volatile("cp.async.cg.shared.global [%0], [%1], 16, %2;" \
        :: "r"(dst), "l"(src), "r"(sz) : "memory")
#define CP_COMMIT() asm volatile("cp.async.commit_group;" ::: "memory")
#define CP_WAIT(n)  asm volatile("cp.async.wait_group %0;" :: "n"(n) : "memory")

// ---------------- bf16-split HMMA GEMM --------------------------------------
// C[M,512] = A[M,K] @ Wt^T + bias (relu opt); A,Wt in hi/lo bf16, K-major.
// CTA tile 256x128x32, 8 warps (warp tile 64x64, grid 4x2), cp.async dbl buf.
// 1 CTA/SM, grid (4,40)=160 CTAs = 1.08 waves.
#define SP 40   // padded smem row stride (bf16 elems)
#define BM 256
#define BN 128
template <int K>
__global__ void __launch_bounds__(256, 1)
k_gemm_mma(const __nv_bfloat16* __restrict__ Ah, const __nv_bfloat16* __restrict__ Al,
           const __nv_bfloat16* __restrict__ Wh, const __nv_bfloat16* __restrict__ Wl,
           const float* __restrict__ bias, float* __restrict__ C, int relu) {
    extern __shared__ __nv_bfloat16 sm[];
    const int M = NN;
    const int NC = K / 32;
    const int ATILE = BM * SP;                    // per hi/lo A tile
    const int BTILE = BN * SP;
    const int STAGE = 2 * ATILE + 2 * BTILE;      // Ah, Al, Bh, Bl

    int tid = threadIdx.x;
    int wid = tid >> 5, lane = tid & 31;
    int wm = wid & 3, wn = wid >> 2;              // warp grid 4(M) x 2(N)
    int bx = blockIdx.x, by = blockIdx.y;

    float acc[4][8][4];
#pragma unroll
    for (int i = 0; i < 4; i++)
#pragma unroll
        for (int j = 0; j < 8; j++)
#pragma unroll
            for (int q = 0; q < 4; q++) acc[i][j][q] = 0.f;

    auto stage_load = [&](int st, int k0) {
        __nv_bfloat16* dst = sm + st * STAGE;
        // A hi/lo: 256 rows x 32 k = 1024 chunks each
#pragma unroll
        for (int t = 0; t < 2; t++) {
            const __nv_bfloat16* src = t ? Al : Ah;
            __nv_bfloat16* d0 = dst + t * ATILE;
#pragma unroll
            for (int it = 0; it < 4; it++) {
                int idx = it * 256 + tid;
                int r = idx >> 2, kc = idx & 3;
                int gr = by * BM + r;
                uint32_t d = smem_u32(d0 + r * SP + kc * 8);
                const __nv_bfloat16* s = src + (size_t)gr * K + k0 + kc * 8;
                int sz = (gr < M) ? 16 : 0;
                CP_ASYNC16(d, s, sz);
            }
        }
        // B hi/lo: 128 rows x 32 k = 512 chunks each
#pragma unroll
        for (int t = 0; t < 2; t++) {
            const __nv_bfloat16* src = t ? Wl : Wh;
            __nv_bfloat16* d0 = dst + 2 * ATILE + t * BTILE;
#pragma unroll
            for (int it = 0; it < 2; it++) {
                int idx = it * 256 + tid;
                int r = idx >> 2, kc = idx & 3;
                int gn = bx * BN + r;
                uint32_t d = smem_u32(d0 + r * SP + kc * 8);
                const __nv_bfloat16* s = src + (size_t)gn * K + k0 + kc * 8;
                CP_ASYNC16(d, s, 16);
            }
        }
    };

    stage_load(0, 0);
    CP_COMMIT();

    for (int i = 0; i < NC; i++) {
        if (i + 1 < NC) { stage_load((i + 1) & 1, (i + 1) * 32); CP_COMMIT(); }
        if (i + 1 < NC) CP_WAIT(1); else CP_WAIT(0);
        __syncthreads();

        __nv_bfloat16* st = sm + (i & 1) * STAGE;
        uint32_t sAh = smem_u32(st);
        uint32_t sAl = smem_u32(st + ATILE);
        uint32_t sBh = smem_u32(st + 2 * ATILE);
        uint32_t sBl = smem_u32(st + 2 * ATILE + BTILE);

#pragma unroll
        for (int ks = 0; ks < 2; ks++) {
            int koff = ks * 16 + (lane >> 4) * 8;
            int arow = wm * 64 + (lane & 15);
            int brow = wn * 64 + (lane & 15);
            uint32_t ah[4][4], al[4][4], bh[4][4], bl[4][4];
#pragma unroll
            for (int mi = 0; mi < 4; mi++) {
                uint32_t ad = (uint32_t)(((arow + mi * 16) * SP + koff) * 2);
                LDSM_X4(ah[mi][0], ah[mi][1], ah[mi][2], ah[mi][3], sAh + ad);
                LDSM_X4(al[mi][0], al[mi][1], al[mi][2], al[mi][3], sAl + ad);
            }
#pragma unroll
            for (int ni = 0; ni < 4; ni++) {
                uint32_t bd = (uint32_t)(((brow + ni * 16) * SP + koff) * 2);
                LDSM_X4(bh[ni][0], bh[ni][1], bh[ni][2], bh[ni][3], sBh + bd);
                LDSM_X4(bl[ni][0], bl[ni][1], bl[ni][2], bl[ni][3], sBl + bd);
            }
#pragma unroll
            for (int mi = 0; mi < 4; mi++)
#pragma unroll
                for (int ni = 0; ni < 4; ni++) {
                    MMA16816(acc[mi][ni * 2 + 0], ah[mi][0], ah[mi][1], ah[mi][2], ah[mi][3],
                             bh[ni][0], bh[ni][2]);
                    MMA16816(acc[mi][ni * 2 + 1], ah[mi][0], ah[mi][1], ah[mi][2], ah[mi][3],
                             bh[ni][1], bh[ni][3]);
                    MMA16816(acc[mi][ni * 2 + 0], ah[mi][0], ah[mi][1], ah[mi][2], ah[mi][3],
                             bl[ni][0], bl[ni][2]);
                    MMA16816(acc[mi][ni * 2 + 1], ah[mi][0], ah[mi][1], ah[mi][2], ah[mi][3],
                             bl[ni][1], bl[ni][3]);
                    MMA16816(acc[mi][ni * 2 + 0], al[mi][0], al[mi][1], al[mi][2], al[mi][3],
                             bh[ni][0], bh[ni][2]);
                    MMA16816(acc[mi][ni * 2 + 1], al[mi][0], al[mi][1], al[mi][2], al[mi][3],
                             bh[ni][1], bh[ni][3]);
                }
        }
        __syncthreads();
    }

    // epilogue
#pragma unroll
    for (int mi = 0; mi < 4; mi++) {
        int grow = by * BM + wm * 64 + mi * 16 + (lane >> 2);
#pragma unroll
        for (int ni = 0; ni < 8; ni++) {
            int gcol = bx * BN + wn * 64 + ni * 8 + (lane & 3) * 2;
            float bx0 = bias[gcol], bx1 = bias[gcol + 1];
            float2 v0, v1;
            v0.x = acc[mi][ni][0] + bx0; v0.y = acc[mi][ni][1] + bx1;
            v1.x = acc[mi][ni][2] + bx0; v1.y = acc[mi][ni][3] + bx1;
            if (relu) {
                v0.x = fmaxf(v0.x, 0.f); v0.y = fmaxf(v0.y, 0.f);
                v1.x = fmaxf(v1.x, 0.f); v1.y = fmaxf(v1.y, 0.f);
            }
            if (grow < M)     *(float2*)(C + (size_t)grow * 512 + gcol) = v0;
            if (grow + 8 < M) *(float2*)(C + (size_t)(grow + 8) * 512 + gcol) = v1;
        }
    }
}

// ---------------- launch ----------------
extern "C" void kernel_launch(void* const* d_in, const int* in_sizes, int n_in,
                              void* d_out, int out_size) {
    const float* x  = (const float*)d_in[0];
    const void*  ei = d_in[1];
    const float* W1 = (const float*)d_in[2];
    const float* b1 = (const float*)d_in[3];
    const float* W2 = (const float*)d_in[4];
    const float* b2 = (const float*)d_in[5];
    const float* W3 = (const float*)d_in[6];
    const float* b3 = (const float*)d_in[7];
    const float* W4 = (const float*)d_in[8];
    const float* b4 = (const float*)d_in[9];
    float* out = (float*)d_out;

    int E = in_sizes[1] / 2;

    float *h;
    __nv_bfloat16 *ah, *al, *wh, *wl;
    cudaGetSymbolAddress((void**)&h,  g_h);
    cudaGetSymbolAddress((void**)&ah, g_ah);
    cudaGetSymbolAddress((void**)&al, g_al);
    cudaGetSymbolAddress((void**)&wh, g_wh);
    cudaGetSymbolAddress((void**)&wl, g_wl);

    const int GSMEM = 2 * (2 * BM * SP + 2 * BN * SP) * 2;   // 122880 B
    static int attr_done = 0;
    if (!attr_done) {
        cudaFuncSetAttribute(k_gemm_mma<256>, cudaFuncAttributeMaxDynamicSharedMemorySize, GSMEM);
        cudaFuncSetAttribute(k_gemm_mma<512>, cudaFuncAttributeMaxDynamicSharedMemorySize, GSMEM);
        attr_done = 1;
    }

    // ---- preprocessing ----
    k_init<<<(NN + 127) / 128, 128>>>(ei, E);
    k_deg<<<(E + 255) / 256, 256>>>(ei, E);
    k_scan<<<1, 1024>>>();
    k_fill<<<(E + NN + 255) / 256, 256>>>(ei, E);
    k_wconv_all<<<dim3(16, 16, 4), dim3(32, 32)>>>(W1, W2, W3, W4, wh, wl);

    dim3 ggrid(4, (NN + BM - 1) / BM);   // (4, 40)

    // ---- layer 1 (K=256) ----
    k_spmm_split<256><<<NN, 64>>>(x, ah, al);
    k_gemm_mma<256><<<ggrid, 256, GSMEM>>>(ah, al, wh + 0 * 512 * 512, wl + 0 * 512 * 512, b1, h, 1);
    // ---- layer 2 ----
    k_spmm_split<512><<<NN, 128>>>(h, ah, al);
    k_gemm_mma<512><<<ggrid, 256, GSMEM>>>(ah, al, wh + 1 * 512 * 512, wl + 1 * 512 * 512, b2, h, 1);
    // ---- layer 3 ----
    k_spmm_split<512><<<NN, 128>>>(h, ah, al);
    k_gemm_mma<512><<<ggrid, 256, GSMEM>>>(ah, al, wh + 2 * 512 * 512, wl + 2 * 512 * 512, b3, h, 1);
    // ---- layer 4 (no relu, to d_out) ----
    k_spmm_split<512><<<NN, 128>>>(h, ah, al);
    k_gemm_mma<512><<<ggrid, 256, GSMEM>>>(ah, al, wh + 3 * 512 * 512, wl + 3 * 512 * 512, b4, out, 0);
}

// round 6
// speedup vs baseline: 1.2461x; 1.2461x over previous
#include <cuda_runtime.h>
#include <cuda_bf16.h>
#include <cstdint>

#define NN    10000
#define EMAXX 160000
#define ETOT  (EMAXX + NN)

// ---------------- device scratch (no allocations allowed) ----------------
__device__ int   g_is64;
__device__ int   g_deg[NN];
__device__ float g_dinv[NN];
__device__ int   g_off[NN + 1];
__device__ int   g_cur[NN];
__device__ int   g_crow[ETOT];
__device__ float g_cnorm[ETOT];
__device__ float g_h[(size_t)NN * 512];               // fp32 activations (GEMM out)
__device__ __nv_bfloat16 g_ah[(size_t)NN * 512];      // A hi (SpMM out)
__device__ __nv_bfloat16 g_al[(size_t)NN * 512];      // A lo
__device__ __nv_bfloat16 g_wh[4 * 512 * 512];         // W^T hi, [N rows][K cols]
__device__ __nv_bfloat16 g_wl[4 * 512 * 512];         // W^T lo

__device__ __forceinline__ int ld_idx(const void* p, long long i) {
    if (g_is64) return (int)((const long long*)p)[i];
    return ((const int*)p)[i];
}

// ---------------- preprocessing (fused) ----------------
__global__ void k_init(const void* ei, int E) {
    int i = blockIdx.x * blockDim.x + threadIdx.x;
    if (i < NN) { g_deg[i] = 1; g_cur[i] = 0; }
    if (blockIdx.x == 0 && threadIdx.x < 32) {
        const long long* p = (const long long*)ei;
        int lim = (E < 64) ? E : 64;
        int bad = 0;
        for (int j = threadIdx.x; j < lim; j += 32) {
            long long v = p[j];
            bad |= (v < 0 || v >= NN);
        }
        unsigned m = __ballot_sync(0xFFFFFFFFu, bad);
        if (threadIdx.x == 0) g_is64 = (m == 0);
    }
}
__global__ void k_deg(const void* ei, int E) {
    int e = blockIdx.x * blockDim.x + threadIdx.x;
    if (e < E) atomicAdd(&g_deg[ld_idx(ei, (long long)E + e)], 1);
}
__global__ void k_scan() {
    __shared__ int s[1024];
    const int CH = 10;
    int t = threadIdx.x;
    int base = t * CH, loc[CH], sum = 0;
#pragma unroll
    for (int j = 0; j < CH; j++) {
        int idx = base + j;
        int v = (idx < NN) ? g_deg[idx] : 0;
        if (idx < NN) g_dinv[idx] = rsqrtf((float)v);
        loc[j] = sum; sum += v;
    }
    s[t] = sum;
    __syncthreads();
    for (int d = 1; d < 1024; d <<= 1) {
        int v = (t >= d) ? s[t - d] : 0;
        __syncthreads();
        s[t] += v;
        __syncthreads();
    }
    int excl = (t > 0) ? s[t - 1] : 0;
#pragma unroll
    for (int j = 0; j < CH; j++) {
        int idx = base + j;
        if (idx < NN) g_off[idx] = excl + loc[j];
    }
    if (t == 0) g_off[NN] = s[1023];
}
__global__ void k_fill(const void* ei, int E) {
    int e = blockIdx.x * blockDim.x + threadIdx.x;
    int tot = E + NN;
    if (e >= tot) return;
    int r, c;
    if (e < E) { r = ld_idx(ei, e); c = ld_idx(ei, (long long)E + e); }
    else { r = e - E; c = r; }
    int p = atomicAdd(&g_cur[c], 1);
    int idx = g_off[c] + p;
    g_crow[idx]  = r;
    g_cnorm[idx] = g_dinv[r] * g_dinv[c];
}

// all 4 weights: W [K,512] fp32 -> Wt hi/lo [512][K] bf16 (tiled transpose)
__global__ void k_wconv_all(const float* __restrict__ W1, const float* __restrict__ W2,
                            const float* __restrict__ W3, const float* __restrict__ W4,
                            __nv_bfloat16* __restrict__ whB, __nv_bfloat16* __restrict__ wlB) {
    __shared__ float t[32][33];
    int l = blockIdx.z;
    const float* W = (l == 0) ? W1 : (l == 1) ? W2 : (l == 2) ? W3 : W4;
    int K = (l == 0) ? 256 : 512;
    int k0 = blockIdx.x * 32, n0 = blockIdx.y * 32;
    if (k0 >= K) return;
    __nv_bfloat16* wh = whB + (size_t)l * 512 * 512;
    __nv_bfloat16* wl = wlB + (size_t)l * 512 * 512;
    int tx = threadIdx.x, ty = threadIdx.y;
    t[ty][tx] = W[(size_t)(k0 + ty) * 512 + n0 + tx];
    __syncthreads();
    float v = t[tx][ty];
    __nv_bfloat16 h = __float2bfloat16(v);
    float lo = v - __bfloat162float(h);
    size_t o = (size_t)(n0 + ty) * K + k0 + tx;
    wh[o] = h;
    wl[o] = __float2bfloat16(lo);
}

// ---------------- SpMM: acc fp32, write bf16 hi/lo split ----------------
__device__ __forceinline__ uint32_t pack2(float a, float b) {
    __nv_bfloat162 t = __floats2bfloat162_rn(a, b);
    return *(uint32_t*)&t;
}
template <int FD>
__global__ void k_spmm_split(const float* __restrict__ h,
                             __nv_bfloat16* __restrict__ ah,
                             __nv_bfloat16* __restrict__ al) {
    const int V = FD / 4;
    int node = blockIdx.x;
    int tid  = threadIdx.x;
    int s = g_off[node], e = g_off[node + 1];
    const float4* h4 = (const float4*)h;
    float4 acc = make_float4(0.f, 0.f, 0.f, 0.f);
    int i = s;
    for (; i + 4 <= e; i += 4) {
        int   r0 = g_crow[i],     r1 = g_crow[i + 1];
        int   r2 = g_crow[i + 2], r3 = g_crow[i + 3];
        float w0 = g_cnorm[i],     w1 = g_cnorm[i + 1];
        float w2 = g_cnorm[i + 2], w3 = g_cnorm[i + 3];
        float4 v0 = h4[(size_t)r0 * V + tid];
        float4 v1 = h4[(size_t)r1 * V + tid];
        float4 v2 = h4[(size_t)r2 * V + tid];
        float4 v3 = h4[(size_t)r3 * V + tid];
        acc.x += w0 * v0.x; acc.y += w0 * v0.y; acc.z += w0 * v0.z; acc.w += w0 * v0.w;
        acc.x += w1 * v1.x; acc.y += w1 * v1.y; acc.z += w1 * v1.z; acc.w += w1 * v1.w;
        acc.x += w2 * v2.x; acc.y += w2 * v2.y; acc.z += w2 * v2.z; acc.w += w2 * v2.w;
        acc.x += w3 * v3.x; acc.y += w3 * v3.y; acc.z += w3 * v3.z; acc.w += w3 * v3.w;
    }
    for (; i < e; i++) {
        int   r = g_crow[i];
        float w = g_cnorm[i];
        float4 v = h4[(size_t)r * V + tid];
        acc.x += w * v.x; acc.y += w * v.y; acc.z += w * v.z; acc.w += w * v.w;
    }
    float hx = __bfloat162float(__float2bfloat16(acc.x));
    float hy = __bfloat162float(__float2bfloat16(acc.y));
    float hz = __bfloat162float(__float2bfloat16(acc.z));
    float hw = __bfloat162float(__float2bfloat16(acc.w));
    uint2 uh, ul;
    uh.x = pack2(acc.x, acc.y); uh.y = pack2(acc.z, acc.w);
    ul.x = pack2(acc.x - hx, acc.y - hy); ul.y = pack2(acc.z - hz, acc.w - hw);
    size_t base = (size_t)node * FD + tid * 4;
    *(uint2*)(ah + base) = uh;
    *(uint2*)(al + base) = ul;
}

// ---------------- HMMA helpers ----------------
__device__ __forceinline__ uint32_t smem_u32(const void* p) {
    uint32_t a;
    asm("{ .reg .u64 t; cvta.to.shared.u64 t, %1; cvt.u32.u64 %0, t; }" : "=r"(a) : "l"(p));
    return a;
}
#define LDSM_X4(r0, r1, r2, r3, addr) \
    asm volatile("ldmatrix.sync.aligned.m8n8.x4.shared.b16 {%0,%1,%2,%3}, [%4];" \
        : "=r"(r0), "=r"(r1), "=r"(r2), "=r"(r3) : "r"(addr))
#define MMA16816(d, a0, a1, a2, a3, b0, b1) \
    asm volatile("mma.sync.aligned.m16n8k16.row.col.f32.bf16.bf16.f32 " \
        "{%0,%1,%2,%3}, {%4,%5,%6,%7}, {%8,%9}, {%0,%1,%2,%3};" \
        : "+f"((d)[0]), "+f"((d)[1]), "+f"((d)[2]), "+f"((d)[3]) \
        : "r"(a0), "r"(a1), "r"(a2), "r"(a3), "r"(b0), "r"(b1))
#define CP_ASYNC16(dst, src, sz) \
    asm volatile("cp.async.cg.shared.global [%0], [%1], 16, %2;" \
        :: "r"(dst), "l"(src), "r"(sz) : "memory")
#define CP_COMMIT() asm volatile("cp.async.commit_group;" ::: "memory")
#define CP_WAIT(n)  asm volatile("cp.async.wait_group %0;" :: "n"(n) : "memory")

// ---------------- bf16-split HMMA GEMM --------------------------------------
// C[M,512] = A[M,K] @ Wt^T + bias (relu opt); A,Wt in hi/lo bf16, K-major.
// CTA tile 128x128x32, 8 warps (warp tile 32x64), cp.async double buffer.
// 2 CTAs/SM; inner loop restructured so live regs ~95 (no spill at 128 cap).
#define SP 40   // padded smem row stride (bf16 elems)
template <int K>
__global__ void __launch_bounds__(256, 2)
k_gemm_mma(const __nv_bfloat16* __restrict__ Ah, const __nv_bfloat16* __restrict__ Al,
           const __nv_bfloat16* __restrict__ Wh, const __nv_bfloat16* __restrict__ Wl,
           const float* __restrict__ bias, float* __restrict__ C, int relu) {
    extern __shared__ __nv_bfloat16 sm[];
    const int M = NN;
    const int NC = K / 32;
    const int TILE = 128 * SP;
    const int STAGE = 4 * TILE;

    int tid = threadIdx.x;
    int wid = tid >> 5, lane = tid & 31;
    int wm = wid & 3, wn = wid >> 2;             // warp grid 4(M) x 2(N)
    int bx = blockIdx.x, by = blockIdx.y;

    float acc[2][8][4];
#pragma unroll
    for (int i = 0; i < 2; i++)
#pragma unroll
        for (int j = 0; j < 8; j++)
#pragma unroll
            for (int q = 0; q < 4; q++) acc[i][j][q] = 0.f;

    auto stage_load = [&](int st, int k0) {
        const __nv_bfloat16* srcs[4] = {Ah, Al, Wh, Wl};
        __nv_bfloat16* dst = sm + st * STAGE;
#pragma unroll
        for (int t = 0; t < 4; t++) {
            const __nv_bfloat16* src = srcs[t];
            bool isA = (t < 2);
            int rowBase = isA ? by * 128 : bx * 128;
#pragma unroll
            for (int it = 0; it < 2; it++) {
                int idx = it * 256 + tid;
                int r = idx >> 2, kc = idx & 3;
                int gr = rowBase + r;
                uint32_t d = smem_u32(dst + t * TILE + r * SP + kc * 8);
                const __nv_bfloat16* s = src + (size_t)gr * K + k0 + kc * 8;
                int sz = (!isA || gr < M) ? 16 : 0;
                CP_ASYNC16(d, s, sz);
            }
        }
    };

    stage_load(0, 0);
    CP_COMMIT();

    for (int i = 0; i < NC; i++) {
        if (i + 1 < NC) { stage_load((i + 1) & 1, (i + 1) * 32); CP_COMMIT(); }
        if (i + 1 < NC) CP_WAIT(1); else CP_WAIT(0);
        __syncthreads();

        __nv_bfloat16* st = sm + (i & 1) * STAGE;
        uint32_t sAh = smem_u32(st);
        uint32_t sAl = smem_u32(st + TILE);
        uint32_t sBh = smem_u32(st + 2 * TILE);
        uint32_t sBl = smem_u32(st + 3 * TILE);

#pragma unroll
        for (int ks = 0; ks < 2; ks++) {
            int koff = ks * 16 + (lane >> 4) * 8;
            int arow = wm * 32 + (lane & 15);
            int brow = wn * 64 + (lane & 15);
            // A frags for this ks (held across ni loop): 16 regs
            uint32_t ah[2][4], al[2][4];
#pragma unroll
            for (int mi = 0; mi < 2; mi++) {
                uint32_t ad = (uint32_t)(((arow + mi * 16) * SP + koff) * 2);
                LDSM_X4(ah[mi][0], ah[mi][1], ah[mi][2], ah[mi][3], sAh + ad);
                LDSM_X4(al[mi][0], al[mi][1], al[mi][2], al[mi][3], sAl + ad);
            }
            // B frags loaded per-ni and consumed immediately: 8 live regs
#pragma unroll
            for (int ni = 0; ni < 4; ni++) {
                uint32_t bd = (uint32_t)(((brow + ni * 16) * SP + koff) * 2);
                uint32_t bh[4], bl[4];
                LDSM_X4(bh[0], bh[1], bh[2], bh[3], sBh + bd);
                LDSM_X4(bl[0], bl[1], bl[2], bl[3], sBl + bd);
#pragma unroll
                for (int mi = 0; mi < 2; mi++) {
                    MMA16816(acc[mi][ni * 2 + 0], ah[mi][0], ah[mi][1], ah[mi][2], ah[mi][3],
                             bh[0], bh[2]);
                    MMA16816(acc[mi][ni * 2 + 1], ah[mi][0], ah[mi][1], ah[mi][2], ah[mi][3],
                             bh[1], bh[3]);
                    MMA16816(acc[mi][ni * 2 + 0], ah[mi][0], ah[mi][1], ah[mi][2], ah[mi][3],
                             bl[0], bl[2]);
                    MMA16816(acc[mi][ni * 2 + 1], ah[mi][0], ah[mi][1], ah[mi][2], ah[mi][3],
                             bl[1], bl[3]);
                    MMA16816(acc[mi][ni * 2 + 0], al[mi][0], al[mi][1], al[mi][2], al[mi][3],
                             bh[0], bh[2]);
                    MMA16816(acc[mi][ni * 2 + 1], al[mi][0], al[mi][1], al[mi][2], al[mi][3],
                             bh[1], bh[3]);
                }
            }
        }
        __syncthreads();
    }

    // epilogue
#pragma unroll
    for (int mi = 0; mi < 2; mi++) {
        int grow = by * 128 + wm * 32 + mi * 16 + (lane >> 2);
#pragma unroll
        for (int ni = 0; ni < 8; ni++) {
            int gcol = bx * 128 + wn * 64 + ni * 8 + (lane & 3) * 2;
            float bx0 = bias[gcol], bx1 = bias[gcol + 1];
            float2 v0, v1;
            v0.x = acc[mi][ni][0] + bx0; v0.y = acc[mi][ni][1] + bx1;
            v1.x = acc[mi][ni][2] + bx0; v1.y = acc[mi][ni][3] + bx1;
            if (relu) {
                v0.x = fmaxf(v0.x, 0.f); v0.y = fmaxf(v0.y, 0.f);
                v1.x = fmaxf(v1.x, 0.f); v1.y = fmaxf(v1.y, 0.f);
            }
            if (grow < M)     *(float2*)(C + (size_t)grow * 512 + gcol) = v0;
            if (grow + 8 < M) *(float2*)(C + (size_t)(grow + 8) * 512 + gcol) = v1;
        }
    }
}

// ---------------- launch ----------------
extern "C" void kernel_launch(void* const* d_in, const int* in_sizes, int n_in,
                              void* d_out, int out_size) {
    const float* x  = (const float*)d_in[0];
    const void*  ei = d_in[1];
    const float* W1 = (const float*)d_in[2];
    const float* b1 = (const float*)d_in[3];
    const float* W2 = (const float*)d_in[4];
    const float* b2 = (const float*)d_in[5];
    const float* W3 = (const float*)d_in[6];
    const float* b3 = (const float*)d_in[7];
    const float* W4 = (const float*)d_in[8];
    const float* b4 = (const float*)d_in[9];
    float* out = (float*)d_out;

    int E = in_sizes[1] / 2;

    float *h;
    __nv_bfloat16 *ah, *al, *wh, *wl;
    cudaGetSymbolAddress((void**)&h,  g_h);
    cudaGetSymbolAddress((void**)&ah, g_ah);
    cudaGetSymbolAddress((void**)&al, g_al);
    cudaGetSymbolAddress((void**)&wh, g_wh);
    cudaGetSymbolAddress((void**)&wl, g_wl);

    const int GSMEM = 2 * 4 * 128 * SP * 2;   // 80KB
    static int attr_done = 0;
    if (!attr_done) {
        cudaFuncSetAttribute(k_gemm_mma<256>, cudaFuncAttributeMaxDynamicSharedMemorySize, GSMEM);
        cudaFuncSetAttribute(k_gemm_mma<512>, cudaFuncAttributeMaxDynamicSharedMemorySize, GSMEM);
        attr_done = 1;
    }

    // ---- preprocessing ----
    k_init<<<(NN + 127) / 128, 128>>>(ei, E);
    k_deg<<<(E + 255) / 256, 256>>>(ei, E);
    k_scan<<<1, 1024>>>();
    k_fill<<<(E + NN + 255) / 256, 256>>>(ei, E);
    k_wconv_all<<<dim3(16, 16, 4), dim3(32, 32)>>>(W1, W2, W3, W4, wh, wl);

    dim3 ggrid(4, (NN + 127) / 128);

    // ---- layer 1 (K=256) ----
    k_spmm_split<256><<<NN, 64>>>(x, ah, al);
    k_gemm_mma<256><<<ggrid, 256, GSMEM>>>(ah, al, wh + 0 * 512 * 512, wl + 0 * 512 * 512, b1, h, 1);
    // ---- layer 2 ----
    k_spmm_split<512><<<NN, 128>>>(h, ah, al);
    k_gemm_mma<512><<<ggrid, 256, GSMEM>>>(ah, al, wh + 1 * 512 * 512, wl + 1 * 512 * 512, b2, h, 1);
    // ---- layer 3 ----
    k_spmm_split<512><<<NN, 128>>>(h, ah, al);
    k_gemm_mma<512><<<ggrid, 256, GSMEM>>>(ah, al, wh + 2 * 512 * 512, wl + 2 * 512 * 512, b3, h, 1);
    // ---- layer 4 (no relu, to d_out) ----
    k_spmm_split<512><<<NN, 128>>>(h, ah, al);
    k_gemm_mma<512><<<ggrid, 256, GSMEM>>>(ah, al, wh + 3 * 512 * 512, wl + 3 * 512 * 512, b4, out, 0);
}

// round 7
// speedup vs baseline: 1.6022x; 1.2857x over previous
#include <cuda_runtime.h>
#include <cuda_bf16.h>
#include <cuda_fp16.h>
#include <cstdint>

#define NN    10000
#define EMAXX 160000
#define ETOT  (EMAXX + NN)

// ---------------- device scratch (no allocations allowed) ----------------
__device__ int   g_is64;
__device__ int   g_deg[NN];
__device__ float g_dinv[NN];
__device__ int   g_off[NN + 1];
__device__ int   g_cur[NN];
__device__ int   g_crow[ETOT];
__device__ float g_cnorm[ETOT];
__device__ float g_h[(size_t)NN * 512];           // fp32 activations (GEMM out)
__device__ __half g_af[(size_t)NN * 512];         // A fp16 (SpMM out)
__device__ __half g_wh[4 * 512 * 512];            // W^T hi fp16, [N rows][K cols]
__device__ __half g_wl[4 * 512 * 512];            // W^T lo fp16 (residual)

__device__ __forceinline__ int ld_idx(const void* p, long long i) {
    if (g_is64) return (int)((const long long*)p)[i];
    return ((const int*)p)[i];
}

// ---------------- preprocessing (fused) ----------------
__global__ void k_init(const void* ei, int E) {
    int i = blockIdx.x * blockDim.x + threadIdx.x;
    if (i < NN) { g_deg[i] = 1; g_cur[i] = 0; }
    if (blockIdx.x == 0 && threadIdx.x < 32) {
        const long long* p = (const long long*)ei;
        int lim = (E < 64) ? E : 64;
        int bad = 0;
        for (int j = threadIdx.x; j < lim; j += 32) {
            long long v = p[j];
            bad |= (v < 0 || v >= NN);
        }
        unsigned m = __ballot_sync(0xFFFFFFFFu, bad);
        if (threadIdx.x == 0) g_is64 = (m == 0);
    }
}
__global__ void k_deg(const void* ei, int E) {
    int e = blockIdx.x * blockDim.x + threadIdx.x;
    if (e < E) atomicAdd(&g_deg[ld_idx(ei, (long long)E + e)], 1);
}
__global__ void k_scan() {
    __shared__ int s[1024];
    const int CH = 10;
    int t = threadIdx.x;
    int base = t * CH, loc[CH], sum = 0;
#pragma unroll
    for (int j = 0; j < CH; j++) {
        int idx = base + j;
        int v = (idx < NN) ? g_deg[idx] : 0;
        if (idx < NN) g_dinv[idx] = rsqrtf((float)v);
        loc[j] = sum; sum += v;
    }
    s[t] = sum;
    __syncthreads();
    for (int d = 1; d < 1024; d <<= 1) {
        int v = (t >= d) ? s[t - d] : 0;
        __syncthreads();
        s[t] += v;
        __syncthreads();
    }
    int excl = (t > 0) ? s[t - 1] : 0;
#pragma unroll
    for (int j = 0; j < CH; j++) {
        int idx = base + j;
        if (idx < NN) g_off[idx] = excl + loc[j];
    }
    if (t == 0) g_off[NN] = s[1023];
}
__global__ void k_fill(const void* ei, int E) {
    int e = blockIdx.x * blockDim.x + threadIdx.x;
    int tot = E + NN;
    if (e >= tot) return;
    int r, c;
    if (e < E) { r = ld_idx(ei, e); c = ld_idx(ei, (long long)E + e); }
    else { r = e - E; c = r; }
    int p = atomicAdd(&g_cur[c], 1);
    int idx = g_off[c] + p;
    g_crow[idx]  = r;
    g_cnorm[idx] = g_dinv[r] * g_dinv[c];
}

// all 4 weights: W [K,512] fp32 -> Wt hi/lo fp16 [512][K] (tiled transpose)
__global__ void k_wconv_all(const float* __restrict__ W1, const float* __restrict__ W2,
                            const float* __restrict__ W3, const float* __restrict__ W4,
                            __half* __restrict__ whB, __half* __restrict__ wlB) {
    __shared__ float t[32][33];
    int l = blockIdx.z;
    const float* W = (l == 0) ? W1 : (l == 1) ? W2 : (l == 2) ? W3 : W4;
    int K = (l == 0) ? 256 : 512;
    int k0 = blockIdx.x * 32, n0 = blockIdx.y * 32;
    if (k0 >= K) return;
    __half* wh = whB + (size_t)l * 512 * 512;
    __half* wl = wlB + (size_t)l * 512 * 512;
    int tx = threadIdx.x, ty = threadIdx.y;
    t[ty][tx] = W[(size_t)(k0 + ty) * 512 + n0 + tx];
    __syncthreads();
    float v = t[tx][ty];                              // = W[k0+tx][n0+ty]
    __half h = __float2half_rn(v);
    float lo = v - __half2float(h);
    size_t o = (size_t)(n0 + ty) * K + k0 + tx;
    wh[o] = h;
    wl[o] = __float2half_rn(lo);
}

// ---------------- SpMM: acc fp32, write fp16 ----------------
__device__ __forceinline__ uint32_t packh2(float a, float b) {
    __half2 t = __floats2half2_rn(a, b);
    return *(uint32_t*)&t;
}
template <int FD>
__global__ void k_spmm_f16(const float* __restrict__ h, __half* __restrict__ af) {
    const int V = FD / 4;
    int node = blockIdx.x;
    int tid  = threadIdx.x;
    int s = g_off[node], e = g_off[node + 1];
    const float4* h4 = (const float4*)h;
    float4 acc = make_float4(0.f, 0.f, 0.f, 0.f);
    int i = s;
    for (; i + 4 <= e; i += 4) {
        int   r0 = g_crow[i],     r1 = g_crow[i + 1];
        int   r2 = g_crow[i + 2], r3 = g_crow[i + 3];
        float w0 = g_cnorm[i],     w1 = g_cnorm[i + 1];
        float w2 = g_cnorm[i + 2], w3 = g_cnorm[i + 3];
        float4 v0 = h4[(size_t)r0 * V + tid];
        float4 v1 = h4[(size_t)r1 * V + tid];
        float4 v2 = h4[(size_t)r2 * V + tid];
        float4 v3 = h4[(size_t)r3 * V + tid];
        acc.x += w0 * v0.x; acc.y += w0 * v0.y; acc.z += w0 * v0.z; acc.w += w0 * v0.w;
        acc.x += w1 * v1.x; acc.y += w1 * v1.y; acc.z += w1 * v1.z; acc.w += w1 * v1.w;
        acc.x += w2 * v2.x; acc.y += w2 * v2.y; acc.z += w2 * v2.z; acc.w += w2 * v2.w;
        acc.x += w3 * v3.x; acc.y += w3 * v3.y; acc.z += w3 * v3.z; acc.w += w3 * v3.w;
    }
    for (; i < e; i++) {
        int   r = g_crow[i];
        float w = g_cnorm[i];
        float4 v = h4[(size_t)r * V + tid];
        acc.x += w * v.x; acc.y += w * v.y; acc.z += w * v.z; acc.w += w * v.w;
    }
    uint2 u;
    u.x = packh2(acc.x, acc.y);
    u.y = packh2(acc.z, acc.w);
    *(uint2*)(af + (size_t)node * FD + tid * 4) = u;
}

// ---------------- HMMA helpers ----------------
__device__ __forceinline__ uint32_t smem_u32(const void* p) {
    uint32_t a;
    asm("{ .reg .u64 t; cvta.to.shared.u64 t, %1; cvt.u32.u64 %0, t; }" : "=r"(a) : "l"(p));
    return a;
}
#define LDSM_X4(r0, r1, r2, r3, addr) \
    asm volatile("ldmatrix.sync.aligned.m8n8.x4.shared.b16 {%0,%1,%2,%3}, [%4];" \
        : "=r"(r0), "=r"(r1), "=r"(r2), "=r"(r3) : "r"(addr))
#define MMA16816F(d, a0, a1, a2, a3, b0, b1) \
    asm volatile("mma.sync.aligned.m16n8k16.row.col.f32.f16.f16.f32 " \
        "{%0,%1,%2,%3}, {%4,%5,%6,%7}, {%8,%9}, {%0,%1,%2,%3};" \
        : "+f"((d)[0]), "+f"((d)[1]), "+f"((d)[2]), "+f"((d)[3]) \
        : "r"(a0), "r"(a1), "r"(a2), "r"(a3), "r"(b0), "r"(b1))
#define CP_ASYNC16(dst, src, sz) \
    asm volatile("cp.async.cg.shared.global [%0], [%1], 16, %2;" \
        :: "r"(dst), "l"(src), "r"(sz) : "memory")
#define CP_COMMIT() asm volatile("cp.async.commit_group;" ::: "memory")
#define CP_WAIT(n)  asm volatile("cp.async.wait_group %0;" :: "n"(n) : "memory")

// ---------------- fp16 2-pass HMMA GEMM -------------------------------------
// C[M,512] = A[M,K] @ (Wh+Wl)^T + bias (relu opt); A fp16, Wh/Wl fp16, K-major.
// CTA tile 128x128x32, 8 warps (warp tile 32x64), cp.async double buffer, 2 CTA/SM.
#define SP 40   // padded smem row stride (fp16 elems)
template <int K>
__global__ void __launch_bounds__(256, 2)
k_gemm_mma(const __half* __restrict__ Af, const __half* __restrict__ Wh,
           const __half* __restrict__ Wl,
           const float* __restrict__ bias, float* __restrict__ C, int relu) {
    extern __shared__ __half sm[];
    const int M = NN;
    const int NC = K / 32;
    const int TILE = 128 * SP;
    const int STAGE = 3 * TILE;                   // Af, Wh, Wl

    int tid = threadIdx.x;
    int wid = tid >> 5, lane = tid & 31;
    int wm = wid & 3, wn = wid >> 2;              // warp grid 4(M) x 2(N)
    int bx = blockIdx.x, by = blockIdx.y;

    float acc[2][8][4];
#pragma unroll
    for (int i = 0; i < 2; i++)
#pragma unroll
        for (int j = 0; j < 8; j++)
#pragma unroll
            for (int q = 0; q < 4; q++) acc[i][j][q] = 0.f;

    auto stage_load = [&](int st, int k0) {
        const __half* srcs[3] = {Af, Wh, Wl};
        __half* dst = sm + st * STAGE;
#pragma unroll
        for (int t = 0; t < 3; t++) {
            const __half* src = srcs[t];
            bool isA = (t == 0);
            int rowBase = isA ? by * 128 : bx * 128;
#pragma unroll
            for (int it = 0; it < 2; it++) {
                int idx = it * 256 + tid;
                int r = idx >> 2, kc = idx & 3;
                int gr = rowBase + r;
                uint32_t d = smem_u32(dst + t * TILE + r * SP + kc * 8);
                const __half* s = src + (size_t)gr * K + k0 + kc * 8;
                int sz = (!isA || gr < M) ? 16 : 0;
                CP_ASYNC16(d, s, sz);
            }
        }
    };

    stage_load(0, 0);
    CP_COMMIT();

    for (int i = 0; i < NC; i++) {
        if (i + 1 < NC) { stage_load((i + 1) & 1, (i + 1) * 32); CP_COMMIT(); }
        if (i + 1 < NC) CP_WAIT(1); else CP_WAIT(0);
        __syncthreads();

        __half* st = sm + (i & 1) * STAGE;
        uint32_t sAf = smem_u32(st);
        uint32_t sBh = smem_u32(st + TILE);
        uint32_t sBl = smem_u32(st + 2 * TILE);

#pragma unroll
        for (int ks = 0; ks < 2; ks++) {
            int koff = ks * 16 + (lane >> 4) * 8;
            int arow = wm * 32 + (lane & 15);
            int brow = wn * 64 + (lane & 15);
            uint32_t ah[2][4];
#pragma unroll
            for (int mi = 0; mi < 2; mi++) {
                uint32_t ad = (uint32_t)(((arow + mi * 16) * SP + koff) * 2);
                LDSM_X4(ah[mi][0], ah[mi][1], ah[mi][2], ah[mi][3], sAf + ad);
            }
#pragma unroll
            for (int ni = 0; ni < 4; ni++) {
                uint32_t bd = (uint32_t)(((brow + ni * 16) * SP + koff) * 2);
                uint32_t bh[4], bl[4];
                LDSM_X4(bh[0], bh[1], bh[2], bh[3], sBh + bd);
                LDSM_X4(bl[0], bl[1], bl[2], bl[3], sBl + bd);
#pragma unroll
                for (int mi = 0; mi < 2; mi++) {
                    MMA16816F(acc[mi][ni * 2 + 0], ah[mi][0], ah[mi][1], ah[mi][2], ah[mi][3],
                              bh[0], bh[2]);
                    MMA16816F(acc[mi][ni * 2 + 1], ah[mi][0], ah[mi][1], ah[mi][2], ah[mi][3],
                              bh[1], bh[3]);
                    MMA16816F(acc[mi][ni * 2 + 0], ah[mi][0], ah[mi][1], ah[mi][2], ah[mi][3],
                              bl[0], bl[2]);
                    MMA16816F(acc[mi][ni * 2 + 1], ah[mi][0], ah[mi][1], ah[mi][2], ah[mi][3],
                              bl[1], bl[3]);
                }
            }
        }
        __syncthreads();
    }

    // epilogue
#pragma unroll
    for (int mi = 0; mi < 2; mi++) {
        int grow = by * 128 + wm * 32 + mi * 16 + (lane >> 2);
#pragma unroll
        for (int ni = 0; ni < 8; ni++) {
            int gcol = bx * 128 + wn * 64 + ni * 8 + (lane & 3) * 2;
            float bx0 = bias[gcol], bx1 = bias[gcol + 1];
            float2 v0, v1;
            v0.x = acc[mi][ni][0] + bx0; v0.y = acc[mi][ni][1] + bx1;
            v1.x = acc[mi][ni][2] + bx0; v1.y = acc[mi][ni][3] + bx1;
            if (relu) {
                v0.x = fmaxf(v0.x, 0.f); v0.y = fmaxf(v0.y, 0.f);
                v1.x = fmaxf(v1.x, 0.f); v1.y = fmaxf(v1.y, 0.f);
            }
            if (grow < M)     *(float2*)(C + (size_t)grow * 512 + gcol) = v0;
            if (grow + 8 < M) *(float2*)(C + (size_t)(grow + 8) * 512 + gcol) = v1;
        }
    }
}

// ---------------- launch ----------------
extern "C" void kernel_launch(void* const* d_in, const int* in_sizes, int n_in,
                              void* d_out, int out_size) {
    const float* x  = (const float*)d_in[0];
    const void*  ei = d_in[1];
    const float* W1 = (const float*)d_in[2];
    const float* b1 = (const float*)d_in[3];
    const float* W2 = (const float*)d_in[4];
    const float* b2 = (const float*)d_in[5];
    const float* W3 = (const float*)d_in[6];
    const float* b3 = (const float*)d_in[7];
    const float* W4 = (const float*)d_in[8];
    const float* b4 = (const float*)d_in[9];
    float* out = (float*)d_out;

    int E = in_sizes[1] / 2;

    float *h;
    __half *af, *wh, *wl;
    cudaGetSymbolAddress((void**)&h,  g_h);
    cudaGetSymbolAddress((void**)&af, g_af);
    cudaGetSymbolAddress((void**)&wh, g_wh);
    cudaGetSymbolAddress((void**)&wl, g_wl);

    const int GSMEM = 2 * 3 * 128 * SP * 2;   // 2 stages * 3 tiles = 61440 B
    static int attr_done = 0;
    if (!attr_done) {
        cudaFuncSetAttribute(k_gemm_mma<256>, cudaFuncAttributeMaxDynamicSharedMemorySize, GSMEM);
        cudaFuncSetAttribute(k_gemm_mma<512>, cudaFuncAttributeMaxDynamicSharedMemorySize, GSMEM);
        attr_done = 1;
    }

    // ---- preprocessing ----
    k_init<<<(NN + 127) / 128, 128>>>(ei, E);
    k_deg<<<(E + 255) / 256, 256>>>(ei, E);
    k_scan<<<1, 1024>>>();
    k_fill<<<(E + NN + 255) / 256, 256>>>(ei, E);
    k_wconv_all<<<dim3(16, 16, 4), dim3(32, 32)>>>(W1, W2, W3, W4, wh, wl);

    dim3 ggrid(4, (NN + 127) / 128);

    // ---- layer 1 (K=256) ----
    k_spmm_f16<256><<<NN, 64>>>(x, af);
    k_gemm_mma<256><<<ggrid, 256, GSMEM>>>(af, wh + 0 * 512 * 512, wl + 0 * 512 * 512, b1, h, 1);
    // ---- layer 2 ----
    k_spmm_f16<512><<<NN, 128>>>(h, af);
    k_gemm_mma<512><<<ggrid, 256, GSMEM>>>(af, wh + 1 * 512 * 512, wl + 1 * 512 * 512, b2, h, 1);
    // ---- layer 3 ----
    k_spmm_f16<512><<<NN, 128>>>(h, af);
    k_gemm_mma<512><<<ggrid, 256, GSMEM>>>(af, wh + 2 * 512 * 512, wl + 2 * 512 * 512, b3, h, 1);
    // ---- layer 4 (no relu, to d_out) ----
    k_spmm_f16<512><<<NN, 128>>>(h, af);
    k_gemm_mma<512><<<ggrid, 256, GSMEM>>>(af, wh + 3 * 512 * 512, wl + 3 * 512 * 512, b4, out, 0);
}

// round 9
// speedup vs baseline: 2.2005x; 1.3735x over previous
#include <cuda_runtime.h>
#include <cuda_bf16.h>
#include <cuda_fp16.h>
#include <cstdint>

#define NN    10000
#define EMAXX 160000
#define ETOT  (EMAXX + NN)

// ---------------- device scratch (no allocations allowed) ----------------
__device__ int   g_is64;
__device__ int   g_deg[NN];
__device__ float g_dinv[NN];
__device__ int   g_off[NN + 1];
__device__ int   g_cur[NN];
__device__ int   g_crow[ETOT];
__device__ float g_cnorm[ETOT];
__device__ __half g_h16[(size_t)NN * 512];        // fp16 activations (GEMM out, relu'd)
__device__ __half g_af[(size_t)NN * 512];         // A fp16 (SpMM out)
__device__ __half g_wh[4 * 512 * 512];            // W^T fp16, [N rows][K cols]

__device__ __forceinline__ int ld_idx(const void* p, long long i) {
    if (g_is64) return (int)((const long long*)p)[i];
    return ((const int*)p)[i];
}

// ---------------- preprocessing (fused) ----------------
__global__ void k_init(const void* ei, int E) {
    int i = blockIdx.x * blockDim.x + threadIdx.x;
    if (i < NN) { g_deg[i] = 1; g_cur[i] = 0; }
    if (blockIdx.x == 0 && threadIdx.x < 32) {
        const long long* p = (const long long*)ei;
        int lim = (E < 64) ? E : 64;
        int bad = 0;
        for (int j = threadIdx.x; j < lim; j += 32) {
            long long v = p[j];
            bad |= (v < 0 || v >= NN);
        }
        unsigned m = __ballot_sync(0xFFFFFFFFu, bad);
        if (threadIdx.x == 0) g_is64 = (m == 0);
    }
}
__global__ void k_deg(const void* ei, int E) {
    int e = blockIdx.x * blockDim.x + threadIdx.x;
    if (e < E) atomicAdd(&g_deg[ld_idx(ei, (long long)E + e)], 1);
}
__global__ void k_scan() {
    __shared__ int s[1024];
    const int CH = 10;
    int t = threadIdx.x;
    int base = t * CH, loc[CH], sum = 0;
#pragma unroll
    for (int j = 0; j < CH; j++) {
        int idx = base + j;
        int v = (idx < NN) ? g_deg[idx] : 0;
        if (idx < NN) g_dinv[idx] = rsqrtf((float)v);
        loc[j] = sum; sum += v;
    }
    s[t] = sum;
    __syncthreads();
    for (int d = 1; d < 1024; d <<= 1) {
        int v = (t >= d) ? s[t - d] : 0;
        __syncthreads();
        s[t] += v;
        __syncthreads();
    }
    int excl = (t > 0) ? s[t - 1] : 0;
#pragma unroll
    for (int j = 0; j < CH; j++) {
        int idx = base + j;
        if (idx < NN) g_off[idx] = excl + loc[j];
    }
    if (t == 0) g_off[NN] = s[1023];
}
__global__ void k_fill(const void* ei, int E) {
    int e = blockIdx.x * blockDim.x + threadIdx.x;
    int tot = E + NN;
    if (e >= tot) return;
    int r, c;
    if (e < E) { r = ld_idx(ei, e); c = ld_idx(ei, (long long)E + e); }
    else { r = e - E; c = r; }
    int p = atomicAdd(&g_cur[c], 1);
    int idx = g_off[c] + p;
    g_crow[idx]  = r;
    g_cnorm[idx] = g_dinv[r] * g_dinv[c];
}

// all 4 weights: W [K,512] fp32 -> Wt fp16 [512][K] (tiled transpose)
__global__ void k_wconv_all(const float* __restrict__ W1, const float* __restrict__ W2,
                            const float* __restrict__ W3, const float* __restrict__ W4,
                            __half* __restrict__ whB) {
    __shared__ float t[32][33];
    int l = blockIdx.z;
    const float* W = (l == 0) ? W1 : (l == 1) ? W2 : (l == 2) ? W3 : W4;
    int K = (l == 0) ? 256 : 512;
    int k0 = blockIdx.x * 32, n0 = blockIdx.y * 32;
    if (k0 >= K) return;
    __half* wh = whB + (size_t)l * 512 * 512;
    int tx = threadIdx.x, ty = threadIdx.y;
    t[ty][tx] = W[(size_t)(k0 + ty) * 512 + n0 + tx];
    __syncthreads();
    wh[(size_t)(n0 + ty) * K + k0 + tx] = __float2half_rn(t[tx][ty]);
}

// ---------------- SpMM: acc fp32, write fp16 ----------------
__device__ __forceinline__ uint32_t packh2(float a, float b) {
    __half2 t = __floats2half2_rn(a, b);
    return *(uint32_t*)&t;
}
// layer 1: fp32 input, FD=256, 64 threads
__global__ void k_spmm_f32in(const float* __restrict__ h, __half* __restrict__ af) {
    const int FD = 256, V = FD / 4;
    int node = blockIdx.x;
    int tid  = threadIdx.x;
    int s = g_off[node], e = g_off[node + 1];
    const float4* h4 = (const float4*)h;
    float4 acc = make_float4(0.f, 0.f, 0.f, 0.f);
    int i = s;
    for (; i + 4 <= e; i += 4) {
        int   r0 = g_crow[i],     r1 = g_crow[i + 1];
        int   r2 = g_crow[i + 2], r3 = g_crow[i + 3];
        float w0 = g_cnorm[i],     w1 = g_cnorm[i + 1];
        float w2 = g_cnorm[i + 2], w3 = g_cnorm[i + 3];
        float4 v0 = h4[(size_t)r0 * V + tid];
        float4 v1 = h4[(size_t)r1 * V + tid];
        float4 v2 = h4[(size_t)r2 * V + tid];
        float4 v3 = h4[(size_t)r3 * V + tid];
        acc.x += w0 * v0.x; acc.y += w0 * v0.y; acc.z += w0 * v0.z; acc.w += w0 * v0.w;
        acc.x += w1 * v1.x; acc.y += w1 * v1.y; acc.z += w1 * v1.z; acc.w += w1 * v1.w;
        acc.x += w2 * v2.x; acc.y += w2 * v2.y; acc.z += w2 * v2.z; acc.w += w2 * v2.w;
        acc.x += w3 * v3.x; acc.y += w3 * v3.y; acc.z += w3 * v3.z; acc.w += w3 * v3.w;
    }
    for (; i < e; i++) {
        int   r = g_crow[i];
        float w = g_cnorm[i];
        float4 v = h4[(size_t)r * V + tid];
        acc.x += w * v.x; acc.y += w * v.y; acc.z += w * v.z; acc.w += w * v.w;
    }
    uint2 u;
    u.x = packh2(acc.x, acc.y);
    u.y = packh2(acc.z, acc.w);
    *(uint2*)(af + (size_t)node * FD + tid * 4) = u;
}
// layers 2-4: fp16 input, FD=512, 128 threads (8B gather per thread)
__global__ void k_spmm_f16in(const __half* __restrict__ h, __half* __restrict__ af) {
    const int FD = 512, V = FD / 4;                // uint2 = 4 halves
    int node = blockIdx.x;
    int tid  = threadIdx.x;
    int s = g_off[node], e = g_off[node + 1];
    const uint2* h4 = (const uint2*)h;
    float4 acc = make_float4(0.f, 0.f, 0.f, 0.f);
    int i = s;
    for (; i + 4 <= e; i += 4) {
        int   r0 = g_crow[i],     r1 = g_crow[i + 1];
        int   r2 = g_crow[i + 2], r3 = g_crow[i + 3];
        float w0 = g_cnorm[i],     w1 = g_cnorm[i + 1];
        float w2 = g_cnorm[i + 2], w3 = g_cnorm[i + 3];
        uint2 u0 = h4[(size_t)r0 * V + tid];
        uint2 u1 = h4[(size_t)r1 * V + tid];
        uint2 u2 = h4[(size_t)r2 * V + tid];
        uint2 u3 = h4[(size_t)r3 * V + tid];
        float2 a0 = __half22float2(*(__half2*)&u0.x), b0 = __half22float2(*(__half2*)&u0.y);
        float2 a1 = __half22float2(*(__half2*)&u1.x), b1 = __half22float2(*(__half2*)&u1.y);
        float2 a2 = __half22float2(*(__half2*)&u2.x), b2 = __half22float2(*(__half2*)&u2.y);
        float2 a3 = __half22float2(*(__half2*)&u3.x), b3 = __half22float2(*(__half2*)&u3.y);
        acc.x += w0 * a0.x; acc.y += w0 * a0.y; acc.z += w0 * b0.x; acc.w += w0 * b0.y;
        acc.x += w1 * a1.x; acc.y += w1 * a1.y; acc.z += w1 * b1.x; acc.w += w1 * b1.y;
        acc.x += w2 * a2.x; acc.y += w2 * a2.y; acc.z += w2 * b2.x; acc.w += w2 * b2.y;
        acc.x += w3 * a3.x; acc.y += w3 * a3.y; acc.z += w3 * b3.x; acc.w += w3 * b3.y;
    }
    for (; i < e; i++) {
        int   r = g_crow[i];
        float w = g_cnorm[i];
        uint2 u0 = h4[(size_t)r * V + tid];
        float2 a0 = __half22float2(*(__half2*)&u0.x), b0 = __half22float2(*(__half2*)&u0.y);
        acc.x += w * a0.x; acc.y += w * a0.y; acc.z += w * b0.x; acc.w += w * b0.y;
    }
    uint2 u;
    u.x = packh2(acc.x, acc.y);
    u.y = packh2(acc.z, acc.w);
    *(uint2*)(af + (size_t)node * FD + tid * 4) = u;
}

// ---------------- HMMA helpers ----------------
__device__ __forceinline__ uint32_t smem_u32(const void* p) {
    uint32_t a;
    asm("{ .reg .u64 t; cvta.to.shared.u64 t, %1; cvt.u32.u64 %0, t; }" : "=r"(a) : "l"(p));
    return a;
}
#define LDSM_X4(r0, r1, r2, r3, addr) \
    asm volatile("ldmatrix.sync.aligned.m8n8.x4.shared.b16 {%0,%1,%2,%3}, [%4];" \
        : "=r"(r0), "=r"(r1), "=r"(r2), "=r"(r3) : "r"(addr))
#define MMA16816F(d, a0, a1, a2, a3, b0, b1) \
    asm volatile("mma.sync.aligned.m16n8k16.row.col.f32.f16.f16.f32 " \
        "{%0,%1,%2,%3}, {%4,%5,%6,%7}, {%8,%9}, {%0,%1,%2,%3};" \
        : "+f"((d)[0]), "+f"((d)[1]), "+f"((d)[2]), "+f"((d)[3]) \
        : "r"(a0), "r"(a1), "r"(a2), "r"(a3), "r"(b0), "r"(b1))
#define CP_ASYNC16(dst, src, sz) \
    asm volatile("cp.async.cg.shared.global [%0], [%1], 16, %2;" \
        :: "r"(dst), "l"(src), "r"(sz) : "memory")
#define CP_COMMIT() asm volatile("cp.async.commit_group;" ::: "memory")
#define CP_WAIT(n)  asm volatile("cp.async.wait_group %0;" :: "n"(n) : "memory")

// ---------------- fp16 single-pass HMMA GEMM --------------------------------
// layers 1-3 (OUT16=1): h16 = relu(A @ Wh^T + bias) fp16
// layer 4   (OUT16=0): out = A @ Wh^T + bias fp32
#define SP 40   // padded smem row stride (fp16 elems)
template <int K, int OUT16>
__global__ void __launch_bounds__(256, 2)
k_gemm_mma(const __half* __restrict__ Af, const __half* __restrict__ Wh,
           const float* __restrict__ bias, void* __restrict__ Cout) {
    extern __shared__ __half sm[];
    const int M = NN;
    const int NC = K / 32;
    const int TILE = 128 * SP;
    const int STAGE = 2 * TILE;                   // Af, Wh

    int tid = threadIdx.x;
    int wid = tid >> 5, lane = tid & 31;
    int wm = wid & 3, wn = wid >> 2;              // warp grid 4(M) x 2(N)
    int bx = blockIdx.x, by = blockIdx.y;

    float acc[2][8][4];
#pragma unroll
    for (int i = 0; i < 2; i++)
#pragma unroll
        for (int j = 0; j < 8; j++)
#pragma unroll
            for (int q = 0; q < 4; q++) acc[i][j][q] = 0.f;

    auto stage_load = [&](int st, int k0) {
        __half* dst = sm + st * STAGE;
#pragma unroll
        for (int t = 0; t < 2; t++) {
            const __half* src = t ? Wh : Af;
            bool isA = (t == 0);
            int rowBase = isA ? by * 128 : bx * 128;
#pragma unroll
            for (int it = 0; it < 2; it++) {
                int idx = it * 256 + tid;
                int r = idx >> 2, kc = idx & 3;
                int gr = rowBase + r;
                uint32_t d = smem_u32(dst + t * TILE + r * SP + kc * 8);
                const __half* s = src + (size_t)gr * K + k0 + kc * 8;
                int sz = (!isA || gr < M) ? 16 : 0;
                CP_ASYNC16(d, s, sz);
            }
        }
    };

    stage_load(0, 0);
    CP_COMMIT();

    for (int i = 0; i < NC; i++) {
        if (i + 1 < NC) { stage_load((i + 1) & 1, (i + 1) * 32); CP_COMMIT(); }
        if (i + 1 < NC) CP_WAIT(1); else CP_WAIT(0);
        __syncthreads();

        __half* st = sm + (i & 1) * STAGE;
        uint32_t sAf = smem_u32(st);
        uint32_t sBh = smem_u32(st + TILE);

#pragma unroll
        for (int ks = 0; ks < 2; ks++) {
            int koff = ks * 16 + (lane >> 4) * 8;
            int arow = wm * 32 + (lane & 15);
            int brow = wn * 64 + (lane & 15);
            uint32_t ah[2][4];
#pragma unroll
            for (int mi = 0; mi < 2; mi++) {
                uint32_t ad = (uint32_t)(((arow + mi * 16) * SP + koff) * 2);
                LDSM_X4(ah[mi][0], ah[mi][1], ah[mi][2], ah[mi][3], sAf + ad);
            }
#pragma unroll
            for (int ni = 0; ni < 4; ni++) {
                uint32_t bd = (uint32_t)(((brow + ni * 16) * SP + koff) * 2);
                uint32_t bh[4];
                LDSM_X4(bh[0], bh[1], bh[2], bh[3], sBh + bd);
#pragma unroll
                for (int mi = 0; mi < 2; mi++) {
                    MMA16816F(acc[mi][ni * 2 + 0], ah[mi][0], ah[mi][1], ah[mi][2], ah[mi][3],
                              bh[0], bh[2]);
                    MMA16816F(acc[mi][ni * 2 + 1], ah[mi][0], ah[mi][1], ah[mi][2], ah[mi][3],
                              bh[1], bh[3]);
                }
            }
        }
        __syncthreads();
    }

    // epilogue
#pragma unroll
    for (int mi = 0; mi < 2; mi++) {
        int grow = by * 128 + wm * 32 + mi * 16 + (lane >> 2);
#pragma unroll
        for (int ni = 0; ni < 8; ni++) {
            int gcol = bx * 128 + wn * 64 + ni * 8 + (lane & 3) * 2;
            float bx0 = bias[gcol], bx1 = bias[gcol + 1];
            float2 v0, v1;
            v0.x = acc[mi][ni][0] + bx0; v0.y = acc[mi][ni][1] + bx1;
            v1.x = acc[mi][ni][2] + bx0; v1.y = acc[mi][ni][3] + bx1;
            if (OUT16) {
                v0.x = fmaxf(v0.x, 0.f); v0.y = fmaxf(v0.y, 0.f);
                v1.x = fmaxf(v1.x, 0.f); v1.y = fmaxf(v1.y, 0.f);
                __half* C16 = (__half*)Cout;
                if (grow < M)
                    *(__half2*)(C16 + (size_t)grow * 512 + gcol) = __floats2half2_rn(v0.x, v0.y);
                if (grow + 8 < M)
                    *(__half2*)(C16 + (size_t)(grow + 8) * 512 + gcol) = __floats2half2_rn(v1.x, v1.y);
            } else {
                float* C = (float*)Cout;
                if (grow < M)     *(float2*)(C + (size_t)grow * 512 + gcol) = v0;
                if (grow + 8 < M) *(float2*)(C + (size_t)(grow + 8) * 512 + gcol) = v1;
            }
        }
    }
}

// ---------------- launch ----------------
extern "C" void kernel_launch(void* const* d_in, const int* in_sizes, int n_in,
                              void* d_out, int out_size) {
    const float* x  = (const float*)d_in[0];
    const void*  ei = d_in[1];
    const float* W1 = (const float*)d_in[2];
    const float* b1 = (const float*)d_in[3];
    const float* W2 = (const float*)d_in[4];
    const float* b2 = (const float*)d_in[5];
    const float* W3 = (const float*)d_in[6];
    const float* b3 = (const float*)d_in[7];
    const float* W4 = (const float*)d_in[8];
    const float* b4 = (const float*)d_in[9];
    float* out = (float*)d_out;

    int E = in_sizes[1] / 2;

    __half *h16, *af, *wh;
    cudaGetSymbolAddress((void**)&h16, g_h16);
    cudaGetSymbolAddress((void**)&af,  g_af);
    cudaGetSymbolAddress((void**)&wh,  g_wh);

    const int GSMEM = 2 * 2 * 128 * SP * 2;   // 2 stages * 2 tiles = 40960 B
    static int attr_done = 0;
    if (!attr_done) {
        cudaFuncSetAttribute((const void*)k_gemm_mma<256, 1>, cudaFuncAttributeMaxDynamicSharedMemorySize, GSMEM);
        cudaFuncSetAttribute((const void*)k_gemm_mma<512, 1>, cudaFuncAttributeMaxDynamicSharedMemorySize, GSMEM);
        cudaFuncSetAttribute((const void*)k_gemm_mma<512, 0>, cudaFuncAttributeMaxDynamicSharedMemorySize, GSMEM);
        attr_done = 1;
    }

    // ---- preprocessing ----
    k_init<<<(NN + 127) / 128, 128>>>(ei, E);
    k_deg<<<(E + 255) / 256, 256>>>(ei, E);
    k_scan<<<1, 1024>>>();
    k_fill<<<(E + NN + 255) / 256, 256>>>(ei, E);
    k_wconv_all<<<dim3(16, 16, 4), dim3(32, 32)>>>(W1, W2, W3, W4, wh);

    dim3 ggrid(4, (NN + 127) / 128);

    // ---- layer 1 (K=256) ----
    k_spmm_f32in<<<NN, 64>>>(x, af);
    k_gemm_mma<256, 1><<<ggrid, 256, GSMEM>>>(af, wh + 0 * 512 * 512, b1, h16);
    // ---- layer 2 ----
    k_spmm_f16in<<<NN, 128>>>(h16, af);
    k_gemm_mma<512, 1><<<ggrid, 256, GSMEM>>>(af, wh + 1 * 512 * 512, b2, h16);
    // ---- layer 3 ----
    k_spmm_f16in<<<NN, 128>>>(h16, af);
    k_gemm_mma<512, 1><<<ggrid, 256, GSMEM>>>(af, wh + 2 * 512 * 512, b3, h16);
    // ---- layer 4 (no relu, fp32 to d_out) ----
    k_spmm_f16in<<<NN, 128>>>(h16, af);
    k_gemm_mma<512, 0><<<ggrid, 256, GSMEM>>>(af, wh + 3 * 512 * 512, b4, out);
}

// round 10
// speedup vs baseline: 2.3474x; 1.0668x over previous
#include <cuda_runtime.h>
#include <cuda_bf16.h>
#include <cuda_fp16.h>
#include <cstdint>

#define NN    10000
#define EMAXX 160000
#define ETOT  (EMAXX + NN)

// ---------------- device scratch (no allocations allowed) ----------------
__device__ int   g_is64;
__device__ int   g_deg[NN];
__device__ float g_dinv[NN];
__device__ int   g_off[NN + 1];
__device__ int   g_cur[NN];
__device__ int   g_crow[ETOT];
__device__ float g_cnorm[ETOT];
__device__ __half g_h16[(size_t)NN * 512];        // fp16 activations (GEMM out, relu'd)
__device__ __half g_af[(size_t)NN * 512];         // A fp16 (SpMM out)
__device__ __half g_wh[4 * 512 * 512];            // W^T fp16, [N rows][K cols]

__device__ __forceinline__ int ld_idx(const void* p, long long i) {
    if (g_is64) return (int)((const long long*)p)[i];
    return ((const int*)p)[i];
}

// ---------------- preprocessing ----------------
__global__ void k_detect(const void* ei, int E) {
    if (threadIdx.x < 32) {
        const long long* p = (const long long*)ei;
        int lim = (E < 64) ? E : 64;
        int bad = 0;
        for (int j = threadIdx.x; j < lim; j += 32) {
            long long v = p[j];
            bad |= (v < 0 || v >= NN);
        }
        unsigned m = __ballot_sync(0xFFFFFFFFu, bad);
        if (threadIdx.x == 0) g_is64 = (m == 0);
    }
}
__global__ void k_deg(const void* ei, int E) {
    int e = blockIdx.x * blockDim.x + threadIdx.x;
    if (e < E) atomicAdd(&g_deg[ld_idx(ei, (long long)E + e)], 1);
}
// single-block scan of (deg+1) -> off, plus dinv   (+1 = self loop)
__global__ void k_scan() {
    __shared__ int s[1024];
    const int CH = 10;
    int t = threadIdx.x;
    int base = t * CH, loc[CH], sum = 0;
#pragma unroll
    for (int j = 0; j < CH; j++) {
        int idx = base + j;
        int v = (idx < NN) ? (g_deg[idx] + 1) : 0;
        if (idx < NN) g_dinv[idx] = rsqrtf((float)v);
        loc[j] = sum; sum += v;
    }
    s[t] = sum;
    __syncthreads();
    for (int d = 1; d < 1024; d <<= 1) {
        int v = (t >= d) ? s[t - d] : 0;
        __syncthreads();
        s[t] += v;
        __syncthreads();
    }
    int excl = (t > 0) ? s[t - 1] : 0;
#pragma unroll
    for (int j = 0; j < CH; j++) {
        int idx = base + j;
        if (idx < NN) g_off[idx] = excl + loc[j];
    }
    if (t == 0) g_off[NN] = s[1023];
}
__global__ void k_fill(const void* ei, int E) {
    int e = blockIdx.x * blockDim.x + threadIdx.x;
    int tot = E + NN;
    if (e >= tot) return;
    int r, c;
    if (e < E) { r = ld_idx(ei, e); c = ld_idx(ei, (long long)E + e); }
    else { r = e - E; c = r; }
    int p = atomicAdd(&g_cur[c], 1);
    int idx = g_off[c] + p;
    g_crow[idx]  = r;
    g_cnorm[idx] = g_dinv[r] * g_dinv[c];
}

// all 4 weights: W [K,512] fp32 -> Wt fp16 [512][K] (tiled transpose)
__global__ void k_wconv_all(const float* __restrict__ W1, const float* __restrict__ W2,
                            const float* __restrict__ W3, const float* __restrict__ W4,
                            __half* __restrict__ whB) {
    __shared__ float t[32][33];
    int l = blockIdx.z;
    const float* W = (l == 0) ? W1 : (l == 1) ? W2 : (l == 2) ? W3 : W4;
    int K = (l == 0) ? 256 : 512;
    int k0 = blockIdx.x * 32, n0 = blockIdx.y * 32;
    if (k0 >= K) return;
    __half* wh = whB + (size_t)l * 512 * 512;
    int tx = threadIdx.x, ty = threadIdx.y;
    t[ty][tx] = W[(size_t)(k0 + ty) * 512 + n0 + tx];
    __syncthreads();
    wh[(size_t)(n0 + ty) * K + k0 + tx] = __float2half_rn(t[tx][ty]);
}

// ---------------- SpMM: acc fp32, write fp16 ----------------
__device__ __forceinline__ uint32_t packh2(float a, float b) {
    __half2 t = __floats2half2_rn(a, b);
    return *(uint32_t*)&t;
}
// layer 1: fp32 input, FD=256, 64 threads
__global__ void k_spmm_f32in(const float* __restrict__ h, __half* __restrict__ af) {
    const int FD = 256, V = FD / 4;
    int node = blockIdx.x;
    int tid  = threadIdx.x;
    int s = g_off[node], e = g_off[node + 1];
    const float4* h4 = (const float4*)h;
    float4 acc = make_float4(0.f, 0.f, 0.f, 0.f);
    int i = s;
    for (; i + 4 <= e; i += 4) {
        int   r0 = g_crow[i],     r1 = g_crow[i + 1];
        int   r2 = g_crow[i + 2], r3 = g_crow[i + 3];
        float w0 = g_cnorm[i],     w1 = g_cnorm[i + 1];
        float w2 = g_cnorm[i + 2], w3 = g_cnorm[i + 3];
        float4 v0 = h4[(size_t)r0 * V + tid];
        float4 v1 = h4[(size_t)r1 * V + tid];
        float4 v2 = h4[(size_t)r2 * V + tid];
        float4 v3 = h4[(size_t)r3 * V + tid];
        acc.x += w0 * v0.x; acc.y += w0 * v0.y; acc.z += w0 * v0.z; acc.w += w0 * v0.w;
        acc.x += w1 * v1.x; acc.y += w1 * v1.y; acc.z += w1 * v1.z; acc.w += w1 * v1.w;
        acc.x += w2 * v2.x; acc.y += w2 * v2.y; acc.z += w2 * v2.z; acc.w += w2 * v2.w;
        acc.x += w3 * v3.x; acc.y += w3 * v3.y; acc.z += w3 * v3.z; acc.w += w3 * v3.w;
    }
    for (; i < e; i++) {
        int   r = g_crow[i];
        float w = g_cnorm[i];
        float4 v = h4[(size_t)r * V + tid];
        acc.x += w * v.x; acc.y += w * v.y; acc.z += w * v.z; acc.w += w * v.w;
    }
    uint2 u;
    u.x = packh2(acc.x, acc.y);
    u.y = packh2(acc.z, acc.w);
    *(uint2*)(af + (size_t)node * FD + tid * 4) = u;
}
// layers 2-4: fp16 input, FD=512, 128 threads (8B gather per thread)
__global__ void k_spmm_f16in(const __half* __restrict__ h, __half* __restrict__ af) {
    const int FD = 512, V = FD / 4;                // uint2 = 4 halves
    int node = blockIdx.x;
    int tid  = threadIdx.x;
    int s = g_off[node], e = g_off[node + 1];
    const uint2* h4 = (const uint2*)h;
    float4 acc = make_float4(0.f, 0.f, 0.f, 0.f);
    int i = s;
    for (; i + 4 <= e; i += 4) {
        int   r0 = g_crow[i],     r1 = g_crow[i + 1];
        int   r2 = g_crow[i + 2], r3 = g_crow[i + 3];
        float w0 = g_cnorm[i],     w1 = g_cnorm[i + 1];
        float w2 = g_cnorm[i + 2], w3 = g_cnorm[i + 3];
        uint2 u0 = h4[(size_t)r0 * V + tid];
        uint2 u1 = h4[(size_t)r1 * V + tid];
        uint2 u2 = h4[(size_t)r2 * V + tid];
        uint2 u3 = h4[(size_t)r3 * V + tid];
        float2 a0 = __half22float2(*(__half2*)&u0.x), b0 = __half22float2(*(__half2*)&u0.y);
        float2 a1 = __half22float2(*(__half2*)&u1.x), b1 = __half22float2(*(__half2*)&u1.y);
        float2 a2 = __half22float2(*(__half2*)&u2.x), b2 = __half22float2(*(__half2*)&u2.y);
        float2 a3 = __half22float2(*(__half2*)&u3.x), b3 = __half22float2(*(__half2*)&u3.y);
        acc.x += w0 * a0.x; acc.y += w0 * a0.y; acc.z += w0 * b0.x; acc.w += w0 * b0.y;
        acc.x += w1 * a1.x; acc.y += w1 * a1.y; acc.z += w1 * b1.x; acc.w += w1 * b1.y;
        acc.x += w2 * a2.x; acc.y += w2 * a2.y; acc.z += w2 * b2.x; acc.w += w2 * b2.y;
        acc.x += w3 * a3.x; acc.y += w3 * a3.y; acc.z += w3 * b3.x; acc.w += w3 * b3.y;
    }
    for (; i < e; i++) {
        int   r = g_crow[i];
        float w = g_cnorm[i];
        uint2 u0 = h4[(size_t)r * V + tid];
        float2 a0 = __half22float2(*(__half2*)&u0.x), b0 = __half22float2(*(__half2*)&u0.y);
        acc.x += w * a0.x; acc.y += w * a0.y; acc.z += w * b0.x; acc.w += w * b0.y;
    }
    uint2 u;
    u.x = packh2(acc.x, acc.y);
    u.y = packh2(acc.z, acc.w);
    *(uint2*)(af + (size_t)node * FD + tid * 4) = u;
}

// ---------------- HMMA helpers ----------------
__device__ __forceinline__ uint32_t smem_u32(const void* p) {
    uint32_t a;
    asm("{ .reg .u64 t; cvta.to.shared.u64 t, %1; cvt.u32.u64 %0, t; }" : "=r"(a) : "l"(p));
    return a;
}
#define LDSM_X4(r0, r1, r2, r3, addr) \
    asm volatile("ldmatrix.sync.aligned.m8n8.x4.shared.b16 {%0,%1,%2,%3}, [%4];" \
        : "=r"(r0), "=r"(r1), "=r"(r2), "=r"(r3) : "r"(addr))
#define MMA16816F(d, a0, a1, a2, a3, b0, b1) \
    asm volatile("mma.sync.aligned.m16n8k16.row.col.f32.f16.f16.f32 " \
        "{%0,%1,%2,%3}, {%4,%5,%6,%7}, {%8,%9}, {%0,%1,%2,%3};" \
        : "+f"((d)[0]), "+f"((d)[1]), "+f"((d)[2]), "+f"((d)[3]) \
        : "r"(a0), "r"(a1), "r"(a2), "r"(a3), "r"(b0), "r"(b1))
#define CP_ASYNC16(dst, src, sz) \
    asm volatile("cp.async.cg.shared.global [%0], [%1], 16, %2;" \
        :: "r"(dst), "l"(src), "r"(sz) : "memory")
#define CP_COMMIT() asm volatile("cp.async.commit_group;" ::: "memory")
#define CP_WAIT(n)  asm volatile("cp.async.wait_group %0;" :: "n"(n) : "memory")

// ---------------- fp16 single-pass HMMA GEMM, K-chunk 64 --------------------
// layers 1-3 (OUT16=1): h16 = relu(A @ Wh^T + bias) fp16
// layer 4   (OUT16=0): out = A @ Wh^T + bias fp32
#define SPAD 72   // padded smem row stride (fp16 elems) for 64-wide K chunk
template <int K, int OUT16>
__global__ void __launch_bounds__(256, 2)
k_gemm_mma(const __half* __restrict__ Af, const __half* __restrict__ Wh,
           const float* __restrict__ bias, void* __restrict__ Cout) {
    extern __shared__ __half sm[];
    const int M = NN;
    const int NC = K / 64;
    const int TILE = 128 * SPAD;
    const int STAGE = 2 * TILE;                   // Af, Wh

    int tid = threadIdx.x;
    int wid = tid >> 5, lane = tid & 31;
    int wm = wid & 3, wn = wid >> 2;              // warp grid 4(M) x 2(N)
    int bx = blockIdx.x, by = blockIdx.y;

    float acc[2][8][4];
#pragma unroll
    for (int i = 0; i < 2; i++)
#pragma unroll
        for (int j = 0; j < 8; j++)
#pragma unroll
            for (int q = 0; q < 4; q++) acc[i][j][q] = 0.f;

    // 128 rows x 64 halves = 8 chunks(16B)/row = 1024 chunks/tile; 4 iters/tile
    auto stage_load = [&](int st, int k0) {
        __half* dst = sm + st * STAGE;
#pragma unroll
        for (int t = 0; t < 2; t++) {
            const __half* src = t ? Wh : Af;
            bool isA = (t == 0);
            int rowBase = isA ? by * 128 : bx * 128;
#pragma unroll
            for (int it = 0; it < 4; it++) {
                int idx = it * 256 + tid;
                int r = idx >> 3, kc = idx & 7;
                int gr = rowBase + r;
                uint32_t d = smem_u32(dst + t * TILE + r * SPAD + kc * 8);
                const __half* s = src + (size_t)gr * K + k0 + kc * 8;
                int sz = (!isA || gr < M) ? 16 : 0;
                CP_ASYNC16(d, s, sz);
            }
        }
    };

    stage_load(0, 0);
    CP_COMMIT();

    for (int i = 0; i < NC; i++) {
        if (i + 1 < NC) { stage_load((i + 1) & 1, (i + 1) * 64); CP_COMMIT(); }
        if (i + 1 < NC) CP_WAIT(1); else CP_WAIT(0);
        __syncthreads();

        __half* st = sm + (i & 1) * STAGE;
        uint32_t sAf = smem_u32(st);
        uint32_t sBh = smem_u32(st + TILE);

#pragma unroll
        for (int ks = 0; ks < 4; ks++) {
            int koff = ks * 16 + (lane >> 4) * 8;
            int arow = wm * 32 + (lane & 15);
            int brow = wn * 64 + (lane & 15);
            uint32_t ah[2][4];
#pragma unroll
            for (int mi = 0; mi < 2; mi++) {
                uint32_t ad = (uint32_t)(((arow + mi * 16) * SPAD + koff) * 2);
                LDSM_X4(ah[mi][0], ah[mi][1], ah[mi][2], ah[mi][3], sAf + ad);
            }
#pragma unroll
            for (int ni = 0; ni < 4; ni++) {
                uint32_t bd = (uint32_t)(((brow + ni * 16) * SPAD + koff) * 2);
                uint32_t bh[4];
                LDSM_X4(bh[0], bh[1], bh[2], bh[3], sBh + bd);
#pragma unroll
                for (int mi = 0; mi < 2; mi++) {
                    MMA16816F(acc[mi][ni * 2 + 0], ah[mi][0], ah[mi][1], ah[mi][2], ah[mi][3],
                              bh[0], bh[2]);
                    MMA16816F(acc[mi][ni * 2 + 1], ah[mi][0], ah[mi][1], ah[mi][2], ah[mi][3],
                              bh[1], bh[3]);
                }
            }
        }
        __syncthreads();
    }

    // epilogue
#pragma unroll
    for (int mi = 0; mi < 2; mi++) {
        int grow = by * 128 + wm * 32 + mi * 16 + (lane >> 2);
#pragma unroll
        for (int ni = 0; ni < 8; ni++) {
            int gcol = bx * 128 + wn * 64 + ni * 8 + (lane & 3) * 2;
            float bx0 = bias[gcol], bx1 = bias[gcol + 1];
            float2 v0, v1;
            v0.x = acc[mi][ni][0] + bx0; v0.y = acc[mi][ni][1] + bx1;
            v1.x = acc[mi][ni][2] + bx0; v1.y = acc[mi][ni][3] + bx1;
            if (OUT16) {
                v0.x = fmaxf(v0.x, 0.f); v0.y = fmaxf(v0.y, 0.f);
                v1.x = fmaxf(v1.x, 0.f); v1.y = fmaxf(v1.y, 0.f);
                __half* C16 = (__half*)Cout;
                if (grow < M)
                    *(__half2*)(C16 + (size_t)grow * 512 + gcol) = __floats2half2_rn(v0.x, v0.y);
                if (grow + 8 < M)
                    *(__half2*)(C16 + (size_t)(grow + 8) * 512 + gcol) = __floats2half2_rn(v1.x, v1.y);
            } else {
                float* C = (float*)Cout;
                if (grow < M)     *(float2*)(C + (size_t)grow * 512 + gcol) = v0;
                if (grow + 8 < M) *(float2*)(C + (size_t)(grow + 8) * 512 + gcol) = v1;
            }
        }
    }
}

// ---------------- launch ----------------
extern "C" void kernel_launch(void* const* d_in, const int* in_sizes, int n_in,
                              void* d_out, int out_size) {
    const float* x  = (const float*)d_in[0];
    const void*  ei = d_in[1];
    const float* W1 = (const float*)d_in[2];
    const float* b1 = (const float*)d_in[3];
    const float* W2 = (const float*)d_in[4];
    const float* b2 = (const float*)d_in[5];
    const float* W3 = (const float*)d_in[6];
    const float* b3 = (const float*)d_in[7];
    const float* W4 = (const float*)d_in[8];
    const float* b4 = (const float*)d_in[9];
    float* out = (float*)d_out;

    int E = in_sizes[1] / 2;

    __half *h16, *af, *wh;
    int *degp, *curp;
    cudaGetSymbolAddress((void**)&h16,  g_h16);
    cudaGetSymbolAddress((void**)&af,   g_af);
    cudaGetSymbolAddress((void**)&wh,   g_wh);
    cudaGetSymbolAddress((void**)&degp, g_deg);
    cudaGetSymbolAddress((void**)&curp, g_cur);

    const int GSMEM = 2 * 2 * 128 * SPAD * 2;   // 2 stages * 2 tiles = 73728 B
    static int attr_done = 0;
    if (!attr_done) {
        cudaFuncSetAttribute((const void*)k_gemm_mma<256, 1>, cudaFuncAttributeMaxDynamicSharedMemorySize, GSMEM);
        cudaFuncSetAttribute((const void*)k_gemm_mma<512, 1>, cudaFuncAttributeMaxDynamicSharedMemorySize, GSMEM);
        cudaFuncSetAttribute((const void*)k_gemm_mma<512, 0>, cudaFuncAttributeMaxDynamicSharedMemorySize, GSMEM);
        attr_done = 1;
    }

    // ---- preprocessing ----
    k_detect<<<1, 32>>>(ei, E);
    cudaMemsetAsync(degp, 0, NN * sizeof(int));
    cudaMemsetAsync(curp, 0, NN * sizeof(int));
    k_deg<<<(E + 255) / 256, 256>>>(ei, E);
    k_scan<<<1, 1024>>>();
    k_fill<<<(E + NN + 255) / 256, 256>>>(ei, E);
    k_wconv_all<<<dim3(16, 16, 4), dim3(32, 32)>>>(W1, W2, W3, W4, wh);

    dim3 ggrid(4, (NN + 127) / 128);

    // ---- layer 1 (K=256) ----
    k_spmm_f32in<<<NN, 64>>>(x, af);
    k_gemm_mma<256, 1><<<ggrid, 256, GSMEM>>>(af, wh + 0 * 512 * 512, b1, h16);
    // ---- layer 2 ----
    k_spmm_f16in<<<NN, 128>>>(h16, af);
    k_gemm_mma<512, 1><<<ggrid, 256, GSMEM>>>(af, wh + 1 * 512 * 512, b2, h16);
    // ---- layer 3 ----
    k_spmm_f16in<<<NN, 128>>>(h16, af);
    k_gemm_mma<512, 1><<<ggrid, 256, GSMEM>>>(af, wh + 2 * 512 * 512, b3, h16);
    // ---- layer 4 (no relu, fp32 to d_out) ----
    k_spmm_f16in<<<NN, 128>>>(h16, af);
    k_gemm_mma<512, 0><<<ggrid, 256, GSMEM>>>(af, wh + 3 * 512 * 512, b4, out);
}